// round 9
// baseline (speedup 1.0000x reference)
#include <cuda_runtime.h>
#include <cuda_bf16.h>
#include <cstdint>

#define XP 136
#define AP 136
#define CP 136

struct Sm {
    __nv_bfloat16 xhi[2][128 * XP];
    __nv_bfloat16 xlo[2][128 * XP];
    __nv_bfloat16 ahi[2][32 * AP];
    __nv_bfloat16 alo[2][32 * AP];
    __nv_bfloat16 chi[32 * CP];
    float x2[2][128];
    float x2p[4 * 128];
    float Spart[16 * 32];
    float Sfin[32];
    float c2[32], scl[32];
};

static __device__ __forceinline__ uint32_t sptr(const void* p) {
    return (uint32_t)__cvta_generic_to_shared(p);
}
static __device__ __forceinline__ void ldsm4(uint32_t* r, uint32_t a) {
    asm volatile("ldmatrix.sync.aligned.m8n8.x4.shared.b16 {%0,%1,%2,%3},[%4];"
                 : "=r"(r[0]), "=r"(r[1]), "=r"(r[2]), "=r"(r[3]) : "r"(a));
}
static __device__ __forceinline__ void ldsm2t(uint32_t* r, uint32_t a) {
    asm volatile("ldmatrix.sync.aligned.m8n8.x2.trans.shared.b16 {%0,%1},[%2];"
                 : "=r"(r[0]), "=r"(r[1]) : "r"(a));
}
static __device__ __forceinline__ void mma16816(float* c, const uint32_t* a, const uint32_t* b) {
    asm volatile(
        "mma.sync.aligned.m16n8k16.row.col.f32.bf16.bf16.f32 "
        "{%0,%1,%2,%3},{%4,%5,%6,%7},{%8,%9},{%0,%1,%2,%3};"
        : "+f"(c[0]), "+f"(c[1]), "+f"(c[2]), "+f"(c[3])
        : "r"(a[0]), "r"(a[1]), "r"(a[2]), "r"(a[3]), "r"(b[0]), "r"(b[1]));
}
static __device__ __forceinline__ void barsync(int id, int cnt) {
    asm volatile("bar.sync %0, %1;" :: "r"(id), "r"(cnt) : "memory");
}
static __device__ __forceinline__ void bararrive(int id, int cnt) {
    asm volatile("bar.arrive %0, %1;" :: "r"(id), "r"(cnt) : "memory");
}

// bars: EMPTY0/1 = 2/3 (640), heavy-internal = 4 (512), prod-internal = 5 (128),
//       FULL0/1 = 6/7 (640)

__global__ void __launch_bounds__(640, 1)
enc_kernel(const float* __restrict__ X, const float* __restrict__ Cg,
           const float* __restrict__ scaleg, float* __restrict__ out)
{
    extern __shared__ char raw[];
    Sm& s = *reinterpret_cast<Sm*>(raw);
    const int tid = threadIdx.x, lane = tid & 31, w = tid >> 5;

    for (int i = tid; i < 4096; i += 640) {
        int k = i >> 7, d = i & 127;
        s.chi[k * CP + d] = __float2bfloat16(Cg[i]);
    }
    if (tid < 32) {
        float c2 = 0.f;
        #pragma unroll 8
        for (int d = 0; d < 128; d++) { float c = Cg[tid * 128 + d]; c2 += c * c; }
        s.c2[tid] = c2;
        s.scl[tid] = scaleg[tid];
    }
    __syncthreads();

    if (w < 4) {
        // ================= PRODUCER (warps 0-3) =================
        int p = 0;
        const int nl = lane * 4;
        for (int u = blockIdx.x; u < 1024; u += gridDim.x) {
            const float* Xb = X + (size_t)(u >> 5) * (128 * 16384);
            const int chn = (u & 31) * 512;
            for (int st = 0; st < 4; st++) {
                const int n0 = chn + st * 128;
                barsync(2 + p, 640);                    // wait buffer empty
                __nv_bfloat16* xh = s.xhi[p];
                __nv_bfloat16* xl = s.xlo[p];
                float p0 = 0.f, p1 = 0.f, p2 = 0.f, p3 = 0.f;
                #pragma unroll 8
                for (int i = 0; i < 32; i++) {
                    const int d = w * 32 + i;
                    float4 v = *reinterpret_cast<const float4*>(Xb + (size_t)d * 16384 + n0 + nl);
                    __nv_bfloat162 H0 = __floats2bfloat162_rn(v.x, v.y);
                    __nv_bfloat162 H1 = __floats2bfloat162_rn(v.z, v.w);
                    float2 h0f = __bfloat1622float2(H0);
                    float2 h1f = __bfloat1622float2(H1);
                    __nv_bfloat162 L0 = __floats2bfloat162_rn(v.x - h0f.x, v.y - h0f.y);
                    __nv_bfloat162 L1 = __floats2bfloat162_rn(v.z - h1f.x, v.w - h1f.y);
                    *reinterpret_cast<__nv_bfloat162*>(&xh[d * XP + nl])     = H0;
                    *reinterpret_cast<__nv_bfloat162*>(&xh[d * XP + nl + 2]) = H1;
                    *reinterpret_cast<__nv_bfloat162*>(&xl[d * XP + nl])     = L0;
                    *reinterpret_cast<__nv_bfloat162*>(&xl[d * XP + nl + 2]) = L1;
                    p0 = fmaf(v.x, v.x, p0); p1 = fmaf(v.y, v.y, p1);
                    p2 = fmaf(v.z, v.z, p2); p3 = fmaf(v.w, v.w, p3);
                }
                *reinterpret_cast<float4*>(&s.x2p[w * 128 + nl]) = make_float4(p0, p1, p2, p3);
                barsync(5, 128);
                s.x2[p][tid] = s.x2p[tid] + s.x2p[128 + tid] + s.x2p[256 + tid] + s.x2p[384 + tid];
                __threadfence_block();
                bararrive(6 + p, 640);                  // signal buffer full
                p ^= 1;
            }
        }
    } else {
        // ================= HEAVY (warps 4-19) =================
        bararrive(2, 640);                              // prime EMPTY0/1
        bararrive(3, 640);
        const int hw = w - 4;                           // 0..15
        const int g = lane >> 2, t = lane & 3;
        const int lr = lane & 15, lh = lane >> 4;
        const int brow = (lane >> 4) * 8 + (lane & 7);
        const int bcol = ((lane >> 3) & 1) * 8;
        const int nb = hw * 8;                          // GEMM1 n-slice (8 wide)
        const int db = (hw >> 1) * 16;                  // GEMM2 d-slice
        const int nh = (hw & 1) * 64;                   // GEMM2 n-half
        const float corr = (hw & 1) ? 0.f : 1.f;        // only even warps apply -S*c
        const float sc0 = s.scl[g],      cc0 = s.c2[g];
        const float sc1 = s.scl[g + 8],  cc1 = s.c2[g + 8];
        const float sc2 = s.scl[g + 16], cc2 = s.c2[g + 16];
        const float sc3 = s.scl[g + 24], cc3 = s.c2[g + 24];

        float e[4][4];
        #pragma unroll
        for (int j = 0; j < 4; j++) { e[j][0] = 0.f; e[j][1] = 0.f; e[j][2] = 0.f; e[j][3] = 0.f; }
        float Sr[4] = {0.f, 0.f, 0.f, 0.f};
        int p = 0;

        for (int u = blockIdx.x; u < 1024; u += gridDim.x) {
            for (int st = 0; st < 4; st++) {
                barsync(6 + p, 640);                    // wait buffer full
                const __nv_bfloat16* xh = s.xhi[p];
                const __nv_bfloat16* xl = s.xlo[p];

                // ---- GEMM1: 32 k x 8 n (this warp's slice) ----
                float acc[2][4];
                acc[0][0] = 0.f; acc[0][1] = 0.f; acc[0][2] = 0.f; acc[0][3] = 0.f;
                acc[1][0] = 0.f; acc[1][1] = 0.f; acc[1][2] = 0.f; acc[1][3] = 0.f;
                #pragma unroll
                for (int kd = 0; kd < 8; kd++) {
                    const int d0 = kd * 16;
                    uint32_t a0[4], a1[4], bh[2];
                    ldsm4(a0, sptr(&s.chi[lr * CP + d0 + lh * 8]));
                    ldsm4(a1, sptr(&s.chi[(16 + lr) * CP + d0 + lh * 8]));
                    ldsm2t(bh, sptr(&xh[(d0 + lr) * XP + nb]));
                    mma16816(acc[0], a0, bh);
                    mma16816(acc[1], a1, bh);
                }

                // ---- in-register softmax over k (per n, 2 n per thread) ----
                float sl[2][4], m[2], sum[2];
                #pragma unroll
                for (int j = 0; j < 2; j++) {
                    const float xv = s.x2[p][nb + 2 * t + j];
                    sl[j][0] = sc0 * (xv - 2.f * acc[0][j]     + cc0);
                    sl[j][1] = sc1 * (xv - 2.f * acc[0][j + 2] + cc1);
                    sl[j][2] = sc2 * (xv - 2.f * acc[1][j]     + cc2);
                    sl[j][3] = sc3 * (xv - 2.f * acc[1][j + 2] + cc3);
                    m[j] = fmaxf(fmaxf(sl[j][0], sl[j][1]), fmaxf(sl[j][2], sl[j][3]));
                    m[j] = fmaxf(m[j], __shfl_xor_sync(0xffffffffu, m[j], 4));
                    m[j] = fmaxf(m[j], __shfl_xor_sync(0xffffffffu, m[j], 8));
                    m[j] = fmaxf(m[j], __shfl_xor_sync(0xffffffffu, m[j], 16));
                    sl[j][0] = __expf(sl[j][0] - m[j]); sl[j][1] = __expf(sl[j][1] - m[j]);
                    sl[j][2] = __expf(sl[j][2] - m[j]); sl[j][3] = __expf(sl[j][3] - m[j]);
                    sum[j] = sl[j][0] + sl[j][1] + sl[j][2] + sl[j][3];
                    sum[j] += __shfl_xor_sync(0xffffffffu, sum[j], 4);
                    sum[j] += __shfl_xor_sync(0xffffffffu, sum[j], 8);
                    sum[j] += __shfl_xor_sync(0xffffffffu, sum[j], 16);
                    const float f = 1.f / sum[j];
                    sl[j][0] *= f; sl[j][1] *= f; sl[j][2] *= f; sl[j][3] *= f;
                    Sr[0] += sl[j][0]; Sr[1] += sl[j][1];
                    Sr[2] += sl[j][2]; Sr[3] += sl[j][3];
                }

                // ---- A-matrix write (double-buffered), conflict-free STS.32 ----
                __nv_bfloat16* ah = s.ahi[p];
                __nv_bfloat16* al = s.alo[p];
                #pragma unroll
                for (int i = 0; i < 4; i++) {
                    const int k = i * 8 + g;
                    const float a0f = sl[0][i], a1f = sl[1][i];
                    __nv_bfloat162 H = __floats2bfloat162_rn(a0f, a1f);
                    float2 hf = __bfloat1622float2(H);
                    __nv_bfloat162 L = __floats2bfloat162_rn(a0f - hf.x, a1f - hf.y);
                    *reinterpret_cast<__nv_bfloat162*>(&ah[k * AP + nb + 2 * t]) = H;
                    *reinterpret_cast<__nv_bfloat162*>(&al[k * AP + nb + 2 * t]) = L;
                }
                barsync(4, 512);   // A complete across heavy warps (drains STS)

                // ---- GEMM2: warp's 16 d rows x 32 k over its 64-n half ----
                #pragma unroll
                for (int kn = 0; kn < 4; kn++) {
                    const int nn = nh + kn * 16;
                    uint32_t Xh[4], Xl[4];
                    ldsm4(Xh, sptr(&xh[(db + lr) * XP + nn + lh * 8]));
                    ldsm4(Xl, sptr(&xl[(db + lr) * XP + nn + lh * 8]));
                    uint32_t b0h[4], b0l[4], b1h[4], b1l[4];
                    ldsm4(b0h, sptr(&ah[brow * AP + nn + bcol]));
                    ldsm4(b0l, sptr(&al[brow * AP + nn + bcol]));
                    ldsm4(b1h, sptr(&ah[(16 + brow) * AP + nn + bcol]));
                    ldsm4(b1l, sptr(&al[(16 + brow) * AP + nn + bcol]));
                    mma16816(e[0], Xh, b0h + 0); mma16816(e[0], Xh, b0l + 0); mma16816(e[0], Xl, b0h + 0);
                    mma16816(e[1], Xh, b0h + 2); mma16816(e[1], Xh, b0l + 2); mma16816(e[1], Xl, b0h + 2);
                    mma16816(e[2], Xh, b1h + 0); mma16816(e[2], Xh, b1l + 0); mma16816(e[2], Xl, b1h + 0);
                    mma16816(e[3], Xh, b1h + 2); mma16816(e[3], Xh, b1l + 2); mma16816(e[3], Xl, b1h + 2);
                }
                bararrive(2 + p, 640);                  // signal buffer empty
                p ^= 1;
            }

            // ---- unit epilogue ----
            #pragma unroll
            for (int i = 0; i < 4; i++) {
                Sr[i] += __shfl_xor_sync(0xffffffffu, Sr[i], 1);
                Sr[i] += __shfl_xor_sync(0xffffffffu, Sr[i], 2);
            }
            if (t == 0) {
                s.Spart[hw * 32 + g]      = Sr[0];
                s.Spart[hw * 32 + g + 8]  = Sr[1];
                s.Spart[hw * 32 + g + 16] = Sr[2];
                s.Spart[hw * 32 + g + 24] = Sr[3];
            }
            Sr[0] = 0.f; Sr[1] = 0.f; Sr[2] = 0.f; Sr[3] = 0.f;
            barsync(4, 512);
            if (hw == 0) {
                float ss = 0.f;
                #pragma unroll
                for (int q = 0; q < 16; q++) ss += s.Spart[q * 32 + lane];
                s.Sfin[lane] = ss;
            }
            barsync(4, 512);
            {
                float* outb = out + (size_t)(u >> 5) * 4096;
                #pragma unroll
                for (int j = 0; j < 4; j++) {
                    const int k0 = j * 8 + 2 * t, d0 = db + g;
                    const float S0 = corr * s.Sfin[k0];
                    const float S1 = corr * s.Sfin[k0 + 1];
                    atomicAdd(&outb[k0 * 128 + d0],            e[j][0] - S0 * Cg[k0 * 128 + d0]);
                    atomicAdd(&outb[(k0 + 1) * 128 + d0],      e[j][1] - S1 * Cg[(k0 + 1) * 128 + d0]);
                    atomicAdd(&outb[k0 * 128 + d0 + 8],        e[j][2] - S0 * Cg[k0 * 128 + d0 + 8]);
                    atomicAdd(&outb[(k0 + 1) * 128 + d0 + 8],  e[j][3] - S1 * Cg[(k0 + 1) * 128 + d0 + 8]);
                    e[j][0] = 0.f; e[j][1] = 0.f; e[j][2] = 0.f; e[j][3] = 0.f;
                }
            }
        }
    }
}

extern "C" void kernel_launch(void* const* d_in, const int* in_sizes, int n_in,
                              void* d_out, int out_size) {
    const float* X  = (const float*)d_in[0];
    const float* C  = (const float*)d_in[1];
    const float* sc = (const float*)d_in[2];
    float* out = (float*)d_out;

    int dev = 0, sms = 0;
    cudaGetDevice(&dev);
    cudaDeviceGetAttribute(&sms, cudaDevAttrMultiProcessorCount, dev);
    if (sms <= 0) sms = 148;

    cudaFuncSetAttribute(enc_kernel, cudaFuncAttributeMaxDynamicSharedMemorySize,
                         (int)sizeof(Sm));
    cudaMemsetAsync(out, 0, (size_t)out_size * sizeof(float));
    enc_kernel<<<sms, 640, sizeof(Sm)>>>(X, C, sc, out);
}

// round 10
// speedup vs baseline: 1.3271x; 1.3271x over previous
#include <cuda_runtime.h>
#include <cuda_bf16.h>
#include <cstdint>

#define XP 136
#define AP 136
#define CP 136

struct Sm {
    __nv_bfloat16 xhi[2][128 * XP];
    __nv_bfloat16 xlo[2][128 * XP];
    __nv_bfloat16 chi[32 * CP];
    __nv_bfloat16 ahi[32 * AP];
    __nv_bfloat16 alo[32 * AP];
    float x2[2][128];
    float x2p[512];
    float Spart[8 * 32];
    float c2[32], scl[32];
};

static __device__ __forceinline__ uint32_t sptr(const void* p) {
    return (uint32_t)__cvta_generic_to_shared(p);
}
static __device__ __forceinline__ void ldsm4(uint32_t* r, uint32_t a) {
    asm volatile("ldmatrix.sync.aligned.m8n8.x4.shared.b16 {%0,%1,%2,%3},[%4];"
                 : "=r"(r[0]), "=r"(r[1]), "=r"(r[2]), "=r"(r[3]) : "r"(a));
}
static __device__ __forceinline__ void ldsm4t(uint32_t* r, uint32_t a) {
    asm volatile("ldmatrix.sync.aligned.m8n8.x4.trans.shared.b16 {%0,%1,%2,%3},[%4];"
                 : "=r"(r[0]), "=r"(r[1]), "=r"(r[2]), "=r"(r[3]) : "r"(a));
}
static __device__ __forceinline__ void mma16816(float* c, const uint32_t* a, const uint32_t* b) {
    asm volatile(
        "mma.sync.aligned.m16n8k16.row.col.f32.bf16.bf16.f32 "
        "{%0,%1,%2,%3},{%4,%5,%6,%7},{%8,%9},{%0,%1,%2,%3};"
        : "+f"(c[0]), "+f"(c[1]), "+f"(c[2]), "+f"(c[3])
        : "r"(a[0]), "r"(a[1]), "r"(a[2]), "r"(a[3]), "r"(b[0]), "r"(b[1]));
}
static __device__ __forceinline__ void barsync(int id, int cnt) {
    asm volatile("bar.sync %0, %1;" :: "r"(id), "r"(cnt) : "memory");
}
static __device__ __forceinline__ void bararrive(int id, int cnt) {
    asm volatile("bar.arrive %0, %1;" :: "r"(id), "r"(cnt) : "memory");
}

// bars: EMPTY0/1=2/3 (384), heavy=4 (256), prod=5 (128), FULL0/1=6/7 (384)

__global__ void __launch_bounds__(384, 1)
enc_kernel(const float* __restrict__ X, const float* __restrict__ Cg,
           const float* __restrict__ scaleg, float* __restrict__ out)
{
    extern __shared__ char raw[];
    Sm& s = *reinterpret_cast<Sm*>(raw);
    const int tid = threadIdx.x, lane = tid & 31, w = tid >> 5;

    for (int i = tid; i < 4096; i += 384) {
        int k = i >> 7, d = i & 127;
        s.chi[k * CP + d] = __float2bfloat16(Cg[i]);
    }
    if (tid < 32) {
        float c2 = 0.f;
        #pragma unroll 8
        for (int d = 0; d < 128; d++) { float c = Cg[tid * 128 + d]; c2 += c * c; }
        s.c2[tid] = c2;
        s.scl[tid] = scaleg[tid];
    }
    __syncthreads();

    const int nq = (1024 - (int)blockIdx.x + (int)gridDim.x - 1) / (int)gridDim.x;
    const int TL = nq * 4;

    if (w < 4) {
        // ================= PRODUCER (warps 0-3), software-pipelined =================
        const int nl = lane * 4;
        float4 va[16];
        {   // prologue: preload batch A of tl=0 (rows w*32+0..15)
            const int u = blockIdx.x;
            const float* base = X + (size_t)(u >> 5) * (128 * 16384) + (u & 31) * 512 + nl;
            #pragma unroll
            for (int i = 0; i < 16; i++)
                va[i] = *reinterpret_cast<const float4*>(base + (size_t)(w * 32 + i) * 16384);
        }
        for (int tl = 0; tl < TL; tl++) {
            const int bi = tl & 1;
            const int u = blockIdx.x + (tl >> 2) * gridDim.x;
            const float* base = X + (size_t)(u >> 5) * (128 * 16384)
                              + (u & 31) * 512 + (tl & 3) * 128 + nl;
            barsync(2 + bi, 384);                      // wait buffer empty
            // issue batch B loads (rows 16..31) immediately — hidden by batch A convert
            float4 vb[16];
            #pragma unroll
            for (int i = 0; i < 16; i++)
                vb[i] = *reinterpret_cast<const float4*>(base + (size_t)(w * 32 + 16 + i) * 16384);
            __nv_bfloat16* xh = s.xhi[bi];
            __nv_bfloat16* xl = s.xlo[bi];
            float p0 = 0.f, p1 = 0.f, p2 = 0.f, p3 = 0.f;
            #pragma unroll
            for (int i = 0; i < 16; i++) {
                const int d = w * 32 + i;
                const float4 v = va[i];
                __nv_bfloat162 H0 = __floats2bfloat162_rn(v.x, v.y);
                __nv_bfloat162 H1 = __floats2bfloat162_rn(v.z, v.w);
                float2 h0f = __bfloat1622float2(H0);
                float2 h1f = __bfloat1622float2(H1);
                __nv_bfloat162 L0 = __floats2bfloat162_rn(v.x - h0f.x, v.y - h0f.y);
                __nv_bfloat162 L1 = __floats2bfloat162_rn(v.z - h1f.x, v.w - h1f.y);
                *reinterpret_cast<__nv_bfloat162*>(&xh[d * XP + nl])     = H0;
                *reinterpret_cast<__nv_bfloat162*>(&xh[d * XP + nl + 2]) = H1;
                *reinterpret_cast<__nv_bfloat162*>(&xl[d * XP + nl])     = L0;
                *reinterpret_cast<__nv_bfloat162*>(&xl[d * XP + nl + 2]) = L1;
                p0 = fmaf(v.x, v.x, p0); p1 = fmaf(v.y, v.y, p1);
                p2 = fmaf(v.z, v.z, p2); p3 = fmaf(v.w, v.w, p3);
            }
            #pragma unroll
            for (int i = 0; i < 16; i++) {
                const int d = w * 32 + 16 + i;
                const float4 v = vb[i];
                __nv_bfloat162 H0 = __floats2bfloat162_rn(v.x, v.y);
                __nv_bfloat162 H1 = __floats2bfloat162_rn(v.z, v.w);
                float2 h0f = __bfloat1622float2(H0);
                float2 h1f = __bfloat1622float2(H1);
                __nv_bfloat162 L0 = __floats2bfloat162_rn(v.x - h0f.x, v.y - h0f.y);
                __nv_bfloat162 L1 = __floats2bfloat162_rn(v.z - h1f.x, v.w - h1f.y);
                *reinterpret_cast<__nv_bfloat162*>(&xh[d * XP + nl])     = H0;
                *reinterpret_cast<__nv_bfloat162*>(&xh[d * XP + nl + 2]) = H1;
                *reinterpret_cast<__nv_bfloat162*>(&xl[d * XP + nl])     = L0;
                *reinterpret_cast<__nv_bfloat162*>(&xl[d * XP + nl + 2]) = L1;
                p0 = fmaf(v.x, v.x, p0); p1 = fmaf(v.y, v.y, p1);
                p2 = fmaf(v.z, v.z, p2); p3 = fmaf(v.w, v.w, p3);
            }
            *reinterpret_cast<float4*>(&s.x2p[w * 128 + nl]) = make_float4(p0, p1, p2, p3);
            barsync(5, 128);
            s.x2[bi][tid] = s.x2p[tid] + s.x2p[128 + tid] + s.x2p[256 + tid] + s.x2p[384 + tid];
            __threadfence_block();
            bararrive(6 + bi, 384);                    // signal buffer full
            // preload batch A for tl+1 — latency overlaps the consumer phase
            if (tl + 1 < TL) {
                const int u2 = blockIdx.x + ((tl + 1) >> 2) * gridDim.x;
                const float* b2 = X + (size_t)(u2 >> 5) * (128 * 16384)
                                + (u2 & 31) * 512 + ((tl + 1) & 3) * 128 + nl;
                #pragma unroll
                for (int i = 0; i < 16; i++)
                    va[i] = *reinterpret_cast<const float4*>(b2 + (size_t)(w * 32 + i) * 16384);
            }
        }
    } else {
        // ================= HEAVY (warps 4-11) =================
        bararrive(2, 384);
        bararrive(3, 384);
        const int hw = w - 4;
        const int g = lane >> 2, t = lane & 3;
        const int lr = lane & 15, lh = lane >> 4;
        const int brow = (lane >> 4) * 8 + (lane & 7);
        const int bcol = ((lane >> 3) & 1) * 8;
        const int nb = hw * 16;
        const float sc0 = s.scl[g],      cc0 = s.c2[g];
        const float sc1 = s.scl[g + 8],  cc1 = s.c2[g + 8];
        const float sc2 = s.scl[g + 16], cc2 = s.c2[g + 16];
        const float sc3 = s.scl[g + 24], cc3 = s.c2[g + 24];

        float e[4][4];
        #pragma unroll
        for (int j = 0; j < 4; j++) { e[j][0] = 0.f; e[j][1] = 0.f; e[j][2] = 0.f; e[j][3] = 0.f; }
        float Sr[4] = {0.f, 0.f, 0.f, 0.f};

        for (int tl = 0; tl < TL; tl++) {
            const int bi = tl & 1;
            const int u = blockIdx.x + (tl >> 2) * gridDim.x;
            barsync(6 + bi, 384);
            const __nv_bfloat16* xh = s.xhi[bi];
            const __nv_bfloat16* xl = s.xlo[bi];

            // ---- GEMM1: all 32 k for this warp's 16 n ----
            float acc[2][2][4];
            #pragma unroll
            for (int mt = 0; mt < 2; mt++)
                #pragma unroll
                for (int nt = 0; nt < 2; nt++) {
                    acc[mt][nt][0] = 0.f; acc[mt][nt][1] = 0.f;
                    acc[mt][nt][2] = 0.f; acc[mt][nt][3] = 0.f;
                }
            #pragma unroll
            for (int kd = 0; kd < 8; kd++) {
                const int d0 = kd * 16;
                uint32_t a0[4], a1[4], bh[4];
                ldsm4(a0, sptr(&s.chi[lr * CP + d0 + lh * 8]));
                ldsm4(a1, sptr(&s.chi[(16 + lr) * CP + d0 + lh * 8]));
                ldsm4t(bh, sptr(&xh[(d0 + lr) * XP + nb + lh * 8]));
                mma16816(acc[0][0], a0, bh + 0);
                mma16816(acc[0][1], a0, bh + 2);
                mma16816(acc[1][0], a1, bh + 0);
                mma16816(acc[1][1], a1, bh + 2);
            }

            // ---- in-register softmax over k ----
            const float* x2 = s.x2[bi];
            float sl[4][4], m[4], sum[4];
            #pragma unroll
            for (int j = 0; j < 4; j++) {
                const int nt = j >> 1, jc = j & 1;
                const float xv = x2[nb + nt * 8 + 2 * t + jc];
                sl[j][0] = sc0 * (xv - 2.f * acc[0][nt][jc]     + cc0);
                sl[j][1] = sc1 * (xv - 2.f * acc[0][nt][jc + 2] + cc1);
                sl[j][2] = sc2 * (xv - 2.f * acc[1][nt][jc]     + cc2);
                sl[j][3] = sc3 * (xv - 2.f * acc[1][nt][jc + 2] + cc3);
                m[j] = fmaxf(fmaxf(sl[j][0], sl[j][1]), fmaxf(sl[j][2], sl[j][3]));
            }
            #pragma unroll
            for (int j = 0; j < 4; j++) {
                m[j] = fmaxf(m[j], __shfl_xor_sync(0xffffffffu, m[j], 4));
                m[j] = fmaxf(m[j], __shfl_xor_sync(0xffffffffu, m[j], 8));
                m[j] = fmaxf(m[j], __shfl_xor_sync(0xffffffffu, m[j], 16));
                sl[j][0] = __expf(sl[j][0] - m[j]); sl[j][1] = __expf(sl[j][1] - m[j]);
                sl[j][2] = __expf(sl[j][2] - m[j]); sl[j][3] = __expf(sl[j][3] - m[j]);
                sum[j] = sl[j][0] + sl[j][1] + sl[j][2] + sl[j][3];
                sum[j] += __shfl_xor_sync(0xffffffffu, sum[j], 4);
                sum[j] += __shfl_xor_sync(0xffffffffu, sum[j], 8);
                sum[j] += __shfl_xor_sync(0xffffffffu, sum[j], 16);
                const float f = 1.f / sum[j];
                sl[j][0] *= f; sl[j][1] *= f; sl[j][2] *= f; sl[j][3] *= f;
                Sr[0] += sl[j][0]; Sr[1] += sl[j][1];
                Sr[2] += sl[j][2]; Sr[3] += sl[j][3];
            }
            // ---- A write (conflict-free STS.32) ----
            #pragma unroll
            for (int i = 0; i < 4; i++) {
                const int k = (i < 2) ? (g + 8 * i) : (16 + g + 8 * (i - 2));
                #pragma unroll
                for (int jp = 0; jp < 2; jp++) {
                    const float a0f = sl[jp * 2 + 0][i], a1f = sl[jp * 2 + 1][i];
                    __nv_bfloat162 H = __floats2bfloat162_rn(a0f, a1f);
                    float2 hf = __bfloat1622float2(H);
                    __nv_bfloat162 L = __floats2bfloat162_rn(a0f - hf.x, a1f - hf.y);
                    *reinterpret_cast<__nv_bfloat162*>(&s.ahi[k * AP + nb + jp * 8 + 2 * t]) = H;
                    *reinterpret_cast<__nv_bfloat162*>(&s.alo[k * AP + nb + jp * 8 + 2 * t]) = L;
                }
            }
            barsync(4, 256);   // A complete

            // ---- GEMM2 ----
            #pragma unroll
            for (int kn = 0; kn < 8; kn++) {
                const int nn = kn * 16;
                uint32_t Xh[4], Xl[4];
                ldsm4(Xh, sptr(&xh[(16 * hw + lr) * XP + nn + lh * 8]));
                ldsm4(Xl, sptr(&xl[(16 * hw + lr) * XP + nn + lh * 8]));
                uint32_t b0h[4], b0l[4], b1h[4], b1l[4];
                ldsm4(b0h, sptr(&s.ahi[brow * AP + nn + bcol]));
                ldsm4(b0l, sptr(&s.alo[brow * AP + nn + bcol]));
                ldsm4(b1h, sptr(&s.ahi[(16 + brow) * AP + nn + bcol]));
                ldsm4(b1l, sptr(&s.alo[(16 + brow) * AP + nn + bcol]));
                mma16816(e[0], Xh, b0h + 0); mma16816(e[0], Xh, b0l + 0); mma16816(e[0], Xl, b0h + 0);
                mma16816(e[1], Xh, b0h + 2); mma16816(e[1], Xh, b0l + 2); mma16816(e[1], Xl, b0h + 2);
                mma16816(e[2], Xh, b1h + 0); mma16816(e[2], Xh, b1l + 0); mma16816(e[2], Xl, b1h + 0);
                mma16816(e[3], Xh, b1h + 2); mma16816(e[3], Xh, b1l + 2); mma16816(e[3], Xl, b1h + 2);
            }
            bararrive(2 + bi, 384);

            // ---- unit epilogue (after 4th subtile of each unit) ----
            if ((tl & 3) == 3) {
                #pragma unroll
                for (int i = 0; i < 4; i++) {
                    Sr[i] += __shfl_xor_sync(0xffffffffu, Sr[i], 1);
                    Sr[i] += __shfl_xor_sync(0xffffffffu, Sr[i], 2);
                }
                if (t == 0) {
                    s.Spart[hw * 32 + g]      = Sr[0];
                    s.Spart[hw * 32 + g + 8]  = Sr[1];
                    s.Spart[hw * 32 + g + 16] = Sr[2];
                    s.Spart[hw * 32 + g + 24] = Sr[3];
                }
                Sr[0] = 0.f; Sr[1] = 0.f; Sr[2] = 0.f; Sr[3] = 0.f;
                barsync(4, 256);
                float* outb = out + (size_t)(u >> 5) * 4096;
                #pragma unroll
                for (int j = 0; j < 4; j++) {
                    const int k0 = j * 8 + 2 * t, d0 = 16 * hw + g;
                    float S0 = 0.f, S1 = 0.f;
                    #pragma unroll
                    for (int q = 0; q < 8; q++) {
                        S0 += s.Spart[q * 32 + k0];
                        S1 += s.Spart[q * 32 + k0 + 1];
                    }
                    atomicAdd(&outb[k0 * 128 + d0],            e[j][0] - S0 * Cg[k0 * 128 + d0]);
                    atomicAdd(&outb[(k0 + 1) * 128 + d0],      e[j][1] - S1 * Cg[(k0 + 1) * 128 + d0]);
                    atomicAdd(&outb[k0 * 128 + d0 + 8],        e[j][2] - S0 * Cg[k0 * 128 + d0 + 8]);
                    atomicAdd(&outb[(k0 + 1) * 128 + d0 + 8],  e[j][3] - S1 * Cg[(k0 + 1) * 128 + d0 + 8]);
                    e[j][0] = 0.f; e[j][1] = 0.f; e[j][2] = 0.f; e[j][3] = 0.f;
                }
            }
        }
    }
}

extern "C" void kernel_launch(void* const* d_in, const int* in_sizes, int n_in,
                              void* d_out, int out_size) {
    const float* X  = (const float*)d_in[0];
    const float* C  = (const float*)d_in[1];
    const float* sc = (const float*)d_in[2];
    float* out = (float*)d_out;

    int dev = 0, sms = 0;
    cudaGetDevice(&dev);
    cudaDeviceGetAttribute(&sms, cudaDevAttrMultiProcessorCount, dev);
    if (sms <= 0) sms = 148;

    cudaFuncSetAttribute(enc_kernel, cudaFuncAttributeMaxDynamicSharedMemorySize,
                         (int)sizeof(Sm));
    cudaMemsetAsync(out, 0, (size_t)out_size * sizeof(float));
    enc_kernel<<<sms, 384, sizeof(Sm)>>>(X, C, sc, out);
}

// round 11
// speedup vs baseline: 1.3846x; 1.0434x over previous
#include <cuda_runtime.h>
#include <cuda_bf16.h>
#include <cstdint>

#define XP 136
#define AP 136
#define CP 136

struct Sm {
    __nv_bfloat16 xhi[2][128 * XP];
    __nv_bfloat16 xlo[2][128 * XP];
    __nv_bfloat16 chi[32 * CP];
    __nv_bfloat16 ahi[32 * AP];
    __nv_bfloat16 alo[32 * AP];
    float x2[2][128];
    float x2p[512];
    float Spart[8 * 32];
    float c2[32], scl[32];
};

static __device__ __forceinline__ uint32_t sptr(const void* p) {
    return (uint32_t)__cvta_generic_to_shared(p);
}
static __device__ __forceinline__ void ldsm4(uint32_t* r, uint32_t a) {
    asm volatile("ldmatrix.sync.aligned.m8n8.x4.shared.b16 {%0,%1,%2,%3},[%4];"
                 : "=r"(r[0]), "=r"(r[1]), "=r"(r[2]), "=r"(r[3]) : "r"(a));
}
static __device__ __forceinline__ void ldsm4t(uint32_t* r, uint32_t a) {
    asm volatile("ldmatrix.sync.aligned.m8n8.x4.trans.shared.b16 {%0,%1,%2,%3},[%4];"
                 : "=r"(r[0]), "=r"(r[1]), "=r"(r[2]), "=r"(r[3]) : "r"(a));
}
static __device__ __forceinline__ void mma16816(float* c, const uint32_t* a, const uint32_t* b) {
    asm volatile(
        "mma.sync.aligned.m16n8k16.row.col.f32.bf16.bf16.f32 "
        "{%0,%1,%2,%3},{%4,%5,%6,%7},{%8,%9},{%0,%1,%2,%3};"
        : "+f"(c[0]), "+f"(c[1]), "+f"(c[2]), "+f"(c[3])
        : "r"(a[0]), "r"(a[1]), "r"(a[2]), "r"(a[3]), "r"(b[0]), "r"(b[1]));
}
static __device__ __forceinline__ void barsync(int id, int cnt) {
    asm volatile("bar.sync %0, %1;" :: "r"(id), "r"(cnt) : "memory");
}
static __device__ __forceinline__ void bararrive(int id, int cnt) {
    asm volatile("bar.arrive %0, %1;" :: "r"(id), "r"(cnt) : "memory");
}

// bars: EMPTY0/1=2/3 (384), heavy=4 (256), prod=5 (128), FULL0/1=6/7 (384)

__global__ void __launch_bounds__(384, 1)
enc_kernel(const float* __restrict__ X, const float* __restrict__ Cg,
           const float* __restrict__ scaleg, float* __restrict__ out)
{
    extern __shared__ char raw[];
    Sm& s = *reinterpret_cast<Sm*>(raw);
    const int tid = threadIdx.x, lane = tid & 31, w = tid >> 5;

    for (int i = tid; i < 4096; i += 384) {
        int k = i >> 7, d = i & 127;
        s.chi[k * CP + d] = __float2bfloat16(Cg[i]);
    }
    if (tid < 32) {
        float c2 = 0.f;
        #pragma unroll 8
        for (int d = 0; d < 128; d++) { float c = Cg[tid * 128 + d]; c2 += c * c; }
        s.c2[tid] = c2;
        s.scl[tid] = scaleg[tid];
    }
    __syncthreads();

    const int nq = (1024 - (int)blockIdx.x + (int)gridDim.x - 1) / (int)gridDim.x;
    const int TL = nq * 4;

    if (w < 4) {
        // ================= PRODUCER (warps 0-3), software-pipelined =================
        const int nl = lane * 4;
        float4 va[16];
        {
            const int u = blockIdx.x;
            const float* base = X + (size_t)(u >> 5) * (128 * 16384) + (u & 31) * 512 + nl;
            #pragma unroll
            for (int i = 0; i < 16; i++)
                va[i] = *reinterpret_cast<const float4*>(base + (size_t)(w * 32 + i) * 16384);
        }
        for (int tl = 0; tl < TL; tl++) {
            const int bi = tl & 1;
            const int u = blockIdx.x + (tl >> 2) * gridDim.x;
            const float* base = X + (size_t)(u >> 5) * (128 * 16384)
                              + (u & 31) * 512 + (tl & 3) * 128 + nl;
            barsync(2 + bi, 384);
            float4 vb[16];
            #pragma unroll
            for (int i = 0; i < 16; i++)
                vb[i] = *reinterpret_cast<const float4*>(base + (size_t)(w * 32 + 16 + i) * 16384);
            __nv_bfloat16* xh = s.xhi[bi];
            __nv_bfloat16* xl = s.xlo[bi];
            float p0 = 0.f, p1 = 0.f, p2 = 0.f, p3 = 0.f;
            #pragma unroll
            for (int i = 0; i < 16; i++) {
                const int d = w * 32 + i;
                const float4 v = va[i];
                __nv_bfloat162 H0 = __floats2bfloat162_rn(v.x, v.y);
                __nv_bfloat162 H1 = __floats2bfloat162_rn(v.z, v.w);
                float2 h0f = __bfloat1622float2(H0);
                float2 h1f = __bfloat1622float2(H1);
                __nv_bfloat162 L0 = __floats2bfloat162_rn(v.x - h0f.x, v.y - h0f.y);
                __nv_bfloat162 L1 = __floats2bfloat162_rn(v.z - h1f.x, v.w - h1f.y);
                *reinterpret_cast<__nv_bfloat162*>(&xh[d * XP + nl])     = H0;
                *reinterpret_cast<__nv_bfloat162*>(&xh[d * XP + nl + 2]) = H1;
                *reinterpret_cast<__nv_bfloat162*>(&xl[d * XP + nl])     = L0;
                *reinterpret_cast<__nv_bfloat162*>(&xl[d * XP + nl + 2]) = L1;
                p0 = fmaf(v.x, v.x, p0); p1 = fmaf(v.y, v.y, p1);
                p2 = fmaf(v.z, v.z, p2); p3 = fmaf(v.w, v.w, p3);
            }
            #pragma unroll
            for (int i = 0; i < 16; i++) {
                const int d = w * 32 + 16 + i;
                const float4 v = vb[i];
                __nv_bfloat162 H0 = __floats2bfloat162_rn(v.x, v.y);
                __nv_bfloat162 H1 = __floats2bfloat162_rn(v.z, v.w);
                float2 h0f = __bfloat1622float2(H0);
                float2 h1f = __bfloat1622float2(H1);
                __nv_bfloat162 L0 = __floats2bfloat162_rn(v.x - h0f.x, v.y - h0f.y);
                __nv_bfloat162 L1 = __floats2bfloat162_rn(v.z - h1f.x, v.w - h1f.y);
                *reinterpret_cast<__nv_bfloat162*>(&xh[d * XP + nl])     = H0;
                *reinterpret_cast<__nv_bfloat162*>(&xh[d * XP + nl + 2]) = H1;
                *reinterpret_cast<__nv_bfloat162*>(&xl[d * XP + nl])     = L0;
                *reinterpret_cast<__nv_bfloat162*>(&xl[d * XP + nl + 2]) = L1;
                p0 = fmaf(v.x, v.x, p0); p1 = fmaf(v.y, v.y, p1);
                p2 = fmaf(v.z, v.z, p2); p3 = fmaf(v.w, v.w, p3);
            }
            *reinterpret_cast<float4*>(&s.x2p[w * 128 + nl]) = make_float4(p0, p1, p2, p3);
            barsync(5, 128);
            s.x2[bi][tid] = s.x2p[tid] + s.x2p[128 + tid] + s.x2p[256 + tid] + s.x2p[384 + tid];
            __threadfence_block();
            bararrive(6 + bi, 384);
            if (tl + 1 < TL) {
                const int u2 = blockIdx.x + ((tl + 1) >> 2) * gridDim.x;
                const float* b2 = X + (size_t)(u2 >> 5) * (128 * 16384)
                                + (u2 & 31) * 512 + ((tl + 1) & 3) * 128 + nl;
                #pragma unroll
                for (int i = 0; i < 16; i++)
                    va[i] = *reinterpret_cast<const float4*>(b2 + (size_t)(w * 32 + i) * 16384);
            }
        }
    } else {
        // ================= HEAVY (warps 4-11) =================
        const int hw = w - 4;
        const int g = lane >> 2, t = lane & 3;
        const int lr = lane & 15, lh = lane >> 4;
        const int brow = (lane >> 4) * 8 + (lane & 7);
        const int bcol = ((lane >> 3) & 1) * 8;
        const int nb = hw * 16;
        const float sc0 = s.scl[g],      cc0 = s.c2[g];
        const float sc1 = s.scl[g + 8],  cc1 = s.c2[g + 8];
        const float sc2 = s.scl[g + 16], cc2 = s.c2[g + 16];
        const float sc3 = s.scl[g + 24], cc3 = s.c2[g + 24];

        // ---- hoist C-fragments into registers (invariant across all subtiles) ----
        uint32_t cfr[8][2][4];
        #pragma unroll
        for (int kd = 0; kd < 8; kd++) {
            ldsm4(cfr[kd][0], sptr(&s.chi[lr * CP + kd * 16 + lh * 8]));
            ldsm4(cfr[kd][1], sptr(&s.chi[(16 + lr) * CP + kd * 16 + lh * 8]));
        }
        bararrive(2, 384);
        bararrive(3, 384);

        float e[4][4];
        #pragma unroll
        for (int j = 0; j < 4; j++) { e[j][0] = 0.f; e[j][1] = 0.f; e[j][2] = 0.f; e[j][3] = 0.f; }
        float Sr[4] = {0.f, 0.f, 0.f, 0.f};

        for (int tl = 0; tl < TL; tl++) {
            const int bi = tl & 1;
            const int u = blockIdx.x + (tl >> 2) * gridDim.x;
            barsync(6 + bi, 384);
            const __nv_bfloat16* xh = s.xhi[bi];
            const __nv_bfloat16* xl = s.xlo[bi];

            // ---- GEMM1: all 32 k for this warp's 16 n (C from registers) ----
            float acc[2][2][4];
            #pragma unroll
            for (int mt = 0; mt < 2; mt++)
                #pragma unroll
                for (int nt = 0; nt < 2; nt++) {
                    acc[mt][nt][0] = 0.f; acc[mt][nt][1] = 0.f;
                    acc[mt][nt][2] = 0.f; acc[mt][nt][3] = 0.f;
                }
            #pragma unroll
            for (int kd = 0; kd < 8; kd++) {
                uint32_t bh[4];
                ldsm4t(bh, sptr(&xh[(kd * 16 + lr) * XP + nb + lh * 8]));
                mma16816(acc[0][0], cfr[kd][0], bh + 0);
                mma16816(acc[0][1], cfr[kd][0], bh + 2);
                mma16816(acc[1][0], cfr[kd][1], bh + 0);
                mma16816(acc[1][1], cfr[kd][1], bh + 2);
            }

            // ---- in-register softmax over k ----
            const float* x2 = s.x2[bi];
            float sl[4][4], m[4], sum[4];
            #pragma unroll
            for (int j = 0; j < 4; j++) {
                const int nt = j >> 1, jc = j & 1;
                const float xv = x2[nb + nt * 8 + 2 * t + jc];
                sl[j][0] = sc0 * (xv - 2.f * acc[0][nt][jc]     + cc0);
                sl[j][1] = sc1 * (xv - 2.f * acc[0][nt][jc + 2] + cc1);
                sl[j][2] = sc2 * (xv - 2.f * acc[1][nt][jc]     + cc2);
                sl[j][3] = sc3 * (xv - 2.f * acc[1][nt][jc + 2] + cc3);
                m[j] = fmaxf(fmaxf(sl[j][0], sl[j][1]), fmaxf(sl[j][2], sl[j][3]));
            }
            #pragma unroll
            for (int j = 0; j < 4; j++) {
                m[j] = fmaxf(m[j], __shfl_xor_sync(0xffffffffu, m[j], 4));
                m[j] = fmaxf(m[j], __shfl_xor_sync(0xffffffffu, m[j], 8));
                m[j] = fmaxf(m[j], __shfl_xor_sync(0xffffffffu, m[j], 16));
                sl[j][0] = __expf(sl[j][0] - m[j]); sl[j][1] = __expf(sl[j][1] - m[j]);
                sl[j][2] = __expf(sl[j][2] - m[j]); sl[j][3] = __expf(sl[j][3] - m[j]);
                sum[j] = sl[j][0] + sl[j][1] + sl[j][2] + sl[j][3];
                sum[j] += __shfl_xor_sync(0xffffffffu, sum[j], 4);
                sum[j] += __shfl_xor_sync(0xffffffffu, sum[j], 8);
                sum[j] += __shfl_xor_sync(0xffffffffu, sum[j], 16);
                const float f = 1.f / sum[j];
                sl[j][0] *= f; sl[j][1] *= f; sl[j][2] *= f; sl[j][3] *= f;
                Sr[0] += sl[j][0]; Sr[1] += sl[j][1];
                Sr[2] += sl[j][2]; Sr[3] += sl[j][3];
            }
            // ---- A write (conflict-free STS.32) ----
            #pragma unroll
            for (int i = 0; i < 4; i++) {
                const int k = (i < 2) ? (g + 8 * i) : (16 + g + 8 * (i - 2));
                #pragma unroll
                for (int jp = 0; jp < 2; jp++) {
                    const float a0f = sl[jp * 2 + 0][i], a1f = sl[jp * 2 + 1][i];
                    __nv_bfloat162 H = __floats2bfloat162_rn(a0f, a1f);
                    float2 hf = __bfloat1622float2(H);
                    __nv_bfloat162 L = __floats2bfloat162_rn(a0f - hf.x, a1f - hf.y);
                    *reinterpret_cast<__nv_bfloat162*>(&s.ahi[k * AP + nb + jp * 8 + 2 * t]) = H;
                    *reinterpret_cast<__nv_bfloat162*>(&s.alo[k * AP + nb + jp * 8 + 2 * t]) = L;
                }
            }
            barsync(4, 256);   // A complete

            // ---- GEMM2 ----
            #pragma unroll
            for (int kn = 0; kn < 8; kn++) {
                const int nn = kn * 16;
                uint32_t Xh[4], Xl[4];
                ldsm4(Xh, sptr(&xh[(16 * hw + lr) * XP + nn + lh * 8]));
                ldsm4(Xl, sptr(&xl[(16 * hw + lr) * XP + nn + lh * 8]));
                uint32_t b0h[4], b0l[4], b1h[4], b1l[4];
                ldsm4(b0h, sptr(&s.ahi[brow * AP + nn + bcol]));
                ldsm4(b0l, sptr(&s.alo[brow * AP + nn + bcol]));
                ldsm4(b1h, sptr(&s.ahi[(16 + brow) * AP + nn + bcol]));
                ldsm4(b1l, sptr(&s.alo[(16 + brow) * AP + nn + bcol]));
                mma16816(e[0], Xh, b0h + 0); mma16816(e[0], Xh, b0l + 0); mma16816(e[0], Xl, b0h + 0);
                mma16816(e[1], Xh, b0h + 2); mma16816(e[1], Xh, b0l + 2); mma16816(e[1], Xl, b0h + 2);
                mma16816(e[2], Xh, b1h + 0); mma16816(e[2], Xh, b1l + 0); mma16816(e[2], Xl, b1h + 0);
                mma16816(e[3], Xh, b1h + 2); mma16816(e[3], Xh, b1l + 2); mma16816(e[3], Xl, b1h + 2);
            }
            bararrive(2 + bi, 384);

            // ---- unit epilogue ----
            if ((tl & 3) == 3) {
                #pragma unroll
                for (int i = 0; i < 4; i++) {
                    Sr[i] += __shfl_xor_sync(0xffffffffu, Sr[i], 1);
                    Sr[i] += __shfl_xor_sync(0xffffffffu, Sr[i], 2);
                }
                if (t == 0) {
                    s.Spart[hw * 32 + g]      = Sr[0];
                    s.Spart[hw * 32 + g + 8]  = Sr[1];
                    s.Spart[hw * 32 + g + 16] = Sr[2];
                    s.Spart[hw * 32 + g + 24] = Sr[3];
                }
                Sr[0] = 0.f; Sr[1] = 0.f; Sr[2] = 0.f; Sr[3] = 0.f;
                barsync(4, 256);
                float* outb = out + (size_t)(u >> 5) * 4096;
                #pragma unroll
                for (int j = 0; j < 4; j++) {
                    const int k0 = j * 8 + 2 * t, d0 = 16 * hw + g;
                    float S0 = 0.f, S1 = 0.f;
                    #pragma unroll
                    for (int q = 0; q < 8; q++) {
                        S0 += s.Spart[q * 32 + k0];
                        S1 += s.Spart[q * 32 + k0 + 1];
                    }
                    atomicAdd(&outb[k0 * 128 + d0],            e[j][0] - S0 * Cg[k0 * 128 + d0]);
                    atomicAdd(&outb[(k0 + 1) * 128 + d0],      e[j][1] - S1 * Cg[(k0 + 1) * 128 + d0]);
                    atomicAdd(&outb[k0 * 128 + d0 + 8],        e[j][2] - S0 * Cg[k0 * 128 + d0 + 8]);
                    atomicAdd(&outb[(k0 + 1) * 128 + d0 + 8],  e[j][3] - S1 * Cg[(k0 + 1) * 128 + d0 + 8]);
                    e[j][0] = 0.f; e[j][1] = 0.f; e[j][2] = 0.f; e[j][3] = 0.f;
                }
            }
        }
    }
}

extern "C" void kernel_launch(void* const* d_in, const int* in_sizes, int n_in,
                              void* d_out, int out_size) {
    const float* X  = (const float*)d_in[0];
    const float* C  = (const float*)d_in[1];
    const float* sc = (const float*)d_in[2];
    float* out = (float*)d_out;

    int dev = 0, sms = 0;
    cudaGetDevice(&dev);
    cudaDeviceGetAttribute(&sms, cudaDevAttrMultiProcessorCount, dev);
    if (sms <= 0) sms = 148;

    cudaFuncSetAttribute(enc_kernel, cudaFuncAttributeMaxDynamicSharedMemorySize,
                         (int)sizeof(Sm));
    cudaMemsetAsync(out, 0, (size_t)out_size * sizeof(float));
    enc_kernel<<<sms, 384, sizeof(Sm)>>>(X, C, sc, out);
}

// round 12
// speedup vs baseline: 1.5674x; 1.1321x over previous
#include <cuda_runtime.h>
#include <cuda_fp16.h>
#include <cstdint>

#define XP 136
#define AP 136
#define CP 136

struct Sm {
    __half xhi[2][128 * XP];
    __half xlo[2][128 * XP];
    __half chi[32 * CP];
    __half ahi[32 * AP];
    float x2[2][128];
    float x2p[512];
    float Spart[8 * 32];
    float c2[32], scl[32];
};

static __device__ __forceinline__ uint32_t sptr(const void* p) {
    return (uint32_t)__cvta_generic_to_shared(p);
}
static __device__ __forceinline__ void ldsm4(uint32_t* r, uint32_t a) {
    asm volatile("ldmatrix.sync.aligned.m8n8.x4.shared.b16 {%0,%1,%2,%3},[%4];"
                 : "=r"(r[0]), "=r"(r[1]), "=r"(r[2]), "=r"(r[3]) : "r"(a));
}
static __device__ __forceinline__ void ldsm4t(uint32_t* r, uint32_t a) {
    asm volatile("ldmatrix.sync.aligned.m8n8.x4.trans.shared.b16 {%0,%1,%2,%3},[%4];"
                 : "=r"(r[0]), "=r"(r[1]), "=r"(r[2]), "=r"(r[3]) : "r"(a));
}
static __device__ __forceinline__ void mma16816(float* c, const uint32_t* a, const uint32_t* b) {
    asm volatile(
        "mma.sync.aligned.m16n8k16.row.col.f32.f16.f16.f32 "
        "{%0,%1,%2,%3},{%4,%5,%6,%7},{%8,%9},{%0,%1,%2,%3};"
        : "+f"(c[0]), "+f"(c[1]), "+f"(c[2]), "+f"(c[3])
        : "r"(a[0]), "r"(a[1]), "r"(a[2]), "r"(a[3]), "r"(b[0]), "r"(b[1]));
}
static __device__ __forceinline__ void barsync(int id, int cnt) {
    asm volatile("bar.sync %0, %1;" :: "r"(id), "r"(cnt) : "memory");
}
static __device__ __forceinline__ void bararrive(int id, int cnt) {
    asm volatile("bar.arrive %0, %1;" :: "r"(id), "r"(cnt) : "memory");
}

// bars: EMPTY0/1=2/3 (384), heavy=4 (256), prod=5 (128), FULL0/1=6/7 (384)

__global__ void __launch_bounds__(384, 1)
enc_kernel(const float* __restrict__ X, const float* __restrict__ Cg,
           const float* __restrict__ scaleg, float* __restrict__ out)
{
    extern __shared__ char raw[];
    Sm& s = *reinterpret_cast<Sm*>(raw);
    const int tid = threadIdx.x, lane = tid & 31, w = tid >> 5;

    for (int i = tid; i < 4096; i += 384) {
        int k = i >> 7, d = i & 127;
        s.chi[k * CP + d] = __float2half(Cg[i]);
    }
    if (tid < 32) {
        float c2 = 0.f;
        #pragma unroll 8
        for (int d = 0; d < 128; d++) { float c = Cg[tid * 128 + d]; c2 += c * c; }
        s.c2[tid] = c2;
        s.scl[tid] = scaleg[tid];
    }
    __syncthreads();

    const int nq = (1024 - (int)blockIdx.x + (int)gridDim.x - 1) / (int)gridDim.x;
    const int TL = nq * 4;

    if (w < 4) {
        // ================= PRODUCER (warps 0-3), software-pipelined =================
        const int nl = lane * 4;
        float4 va[16];
        {
            const int u = blockIdx.x;
            const float* base = X + (size_t)(u >> 5) * (128 * 16384) + (u & 31) * 512 + nl;
            #pragma unroll
            for (int i = 0; i < 16; i++)
                va[i] = *reinterpret_cast<const float4*>(base + (size_t)(w * 32 + i) * 16384);
        }
        for (int tl = 0; tl < TL; tl++) {
            const int bi = tl & 1;
            const int u = blockIdx.x + (tl >> 2) * gridDim.x;
            const float* base = X + (size_t)(u >> 5) * (128 * 16384)
                              + (u & 31) * 512 + (tl & 3) * 128 + nl;
            barsync(2 + bi, 384);
            float4 vb[16];
            #pragma unroll
            for (int i = 0; i < 16; i++)
                vb[i] = *reinterpret_cast<const float4*>(base + (size_t)(w * 32 + 16 + i) * 16384);
            __half* xh = s.xhi[bi];
            __half* xl = s.xlo[bi];
            float p0 = 0.f, p1 = 0.f, p2 = 0.f, p3 = 0.f;
            #pragma unroll
            for (int i = 0; i < 16; i++) {
                const int d = w * 32 + i;
                const float4 v = va[i];
                __half2 H0 = __floats2half2_rn(v.x, v.y);
                __half2 H1 = __floats2half2_rn(v.z, v.w);
                float2 h0f = __half22float2(H0);
                float2 h1f = __half22float2(H1);
                __half2 L0 = __floats2half2_rn(v.x - h0f.x, v.y - h0f.y);
                __half2 L1 = __floats2half2_rn(v.z - h1f.x, v.w - h1f.y);
                *reinterpret_cast<__half2*>(&xh[d * XP + nl])     = H0;
                *reinterpret_cast<__half2*>(&xh[d * XP + nl + 2]) = H1;
                *reinterpret_cast<__half2*>(&xl[d * XP + nl])     = L0;
                *reinterpret_cast<__half2*>(&xl[d * XP + nl + 2]) = L1;
                p0 = fmaf(v.x, v.x, p0); p1 = fmaf(v.y, v.y, p1);
                p2 = fmaf(v.z, v.z, p2); p3 = fmaf(v.w, v.w, p3);
            }
            #pragma unroll
            for (int i = 0; i < 16; i++) {
                const int d = w * 32 + 16 + i;
                const float4 v = vb[i];
                __half2 H0 = __floats2half2_rn(v.x, v.y);
                __half2 H1 = __floats2half2_rn(v.z, v.w);
                float2 h0f = __half22float2(H0);
                float2 h1f = __half22float2(H1);
                __half2 L0 = __floats2half2_rn(v.x - h0f.x, v.y - h0f.y);
                __half2 L1 = __floats2half2_rn(v.z - h1f.x, v.w - h1f.y);
                *reinterpret_cast<__half2*>(&xh[d * XP + nl])     = H0;
                *reinterpret_cast<__half2*>(&xh[d * XP + nl + 2]) = H1;
                *reinterpret_cast<__half2*>(&xl[d * XP + nl])     = L0;
                *reinterpret_cast<__half2*>(&xl[d * XP + nl + 2]) = L1;
                p0 = fmaf(v.x, v.x, p0); p1 = fmaf(v.y, v.y, p1);
                p2 = fmaf(v.z, v.z, p2); p3 = fmaf(v.w, v.w, p3);
            }
            *reinterpret_cast<float4*>(&s.x2p[w * 128 + nl]) = make_float4(p0, p1, p2, p3);
            barsync(5, 128);
            s.x2[bi][tid] = s.x2p[tid] + s.x2p[128 + tid] + s.x2p[256 + tid] + s.x2p[384 + tid];
            __threadfence_block();
            bararrive(6 + bi, 384);
            if (tl + 1 < TL) {
                const int u2 = blockIdx.x + ((tl + 1) >> 2) * gridDim.x;
                const float* b2 = X + (size_t)(u2 >> 5) * (128 * 16384)
                                + (u2 & 31) * 512 + ((tl + 1) & 3) * 128 + nl;
                #pragma unroll
                for (int i = 0; i < 16; i++)
                    va[i] = *reinterpret_cast<const float4*>(b2 + (size_t)(w * 32 + i) * 16384);
            }
        }
    } else {
        // ================= HEAVY (warps 4-11) =================
        const int hw = w - 4;
        const int g = lane >> 2, t = lane & 3;
        const int lr = lane & 15, lh = lane >> 4;
        const int brow = (lane >> 4) * 8 + (lane & 7);
        const int bcol = ((lane >> 3) & 1) * 8;
        const int nb = hw * 16;
        const float sc0 = s.scl[g],      cc0 = s.c2[g];
        const float sc1 = s.scl[g + 8],  cc1 = s.c2[g + 8];
        const float sc2 = s.scl[g + 16], cc2 = s.c2[g + 16];
        const float sc3 = s.scl[g + 24], cc3 = s.c2[g + 24];

        // ---- hoist C-fragments into registers (invariant across subtiles) ----
        uint32_t cfr[8][2][4];
        #pragma unroll
        for (int kd = 0; kd < 8; kd++) {
            ldsm4(cfr[kd][0], sptr(&s.chi[lr * CP + kd * 16 + lh * 8]));
            ldsm4(cfr[kd][1], sptr(&s.chi[(16 + lr) * CP + kd * 16 + lh * 8]));
        }
        bararrive(2, 384);
        bararrive(3, 384);

        float e[4][4];
        #pragma unroll
        for (int j = 0; j < 4; j++) { e[j][0] = 0.f; e[j][1] = 0.f; e[j][2] = 0.f; e[j][3] = 0.f; }
        float Sr[4] = {0.f, 0.f, 0.f, 0.f};

        for (int tl = 0; tl < TL; tl++) {
            const int bi = tl & 1;
            const int u = blockIdx.x + (tl >> 2) * gridDim.x;
            barsync(6 + bi, 384);
            const __half* xh = s.xhi[bi];
            const __half* xl = s.xlo[bi];

            // ---- GEMM1: all 32 k for this warp's 16 n ----
            float acc[2][2][4];
            #pragma unroll
            for (int mt = 0; mt < 2; mt++)
                #pragma unroll
                for (int nt = 0; nt < 2; nt++) {
                    acc[mt][nt][0] = 0.f; acc[mt][nt][1] = 0.f;
                    acc[mt][nt][2] = 0.f; acc[mt][nt][3] = 0.f;
                }
            #pragma unroll
            for (int kd = 0; kd < 8; kd++) {
                uint32_t bh[4];
                ldsm4t(bh, sptr(&xh[(kd * 16 + lr) * XP + nb + lh * 8]));
                mma16816(acc[0][0], cfr[kd][0], bh + 0);
                mma16816(acc[0][1], cfr[kd][0], bh + 2);
                mma16816(acc[1][0], cfr[kd][1], bh + 0);
                mma16816(acc[1][1], cfr[kd][1], bh + 2);
            }

            // ---- in-register softmax over k ----
            const float* x2 = s.x2[bi];
            float sl[4][4], m[4], sum[4];
            #pragma unroll
            for (int j = 0; j < 4; j++) {
                const int nt = j >> 1, jc = j & 1;
                const float xv = x2[nb + nt * 8 + 2 * t + jc];
                sl[j][0] = sc0 * (xv - 2.f * acc[0][nt][jc]     + cc0);
                sl[j][1] = sc1 * (xv - 2.f * acc[0][nt][jc + 2] + cc1);
                sl[j][2] = sc2 * (xv - 2.f * acc[1][nt][jc]     + cc2);
                sl[j][3] = sc3 * (xv - 2.f * acc[1][nt][jc + 2] + cc3);
                m[j] = fmaxf(fmaxf(sl[j][0], sl[j][1]), fmaxf(sl[j][2], sl[j][3]));
            }
            #pragma unroll
            for (int j = 0; j < 4; j++) {
                m[j] = fmaxf(m[j], __shfl_xor_sync(0xffffffffu, m[j], 4));
                m[j] = fmaxf(m[j], __shfl_xor_sync(0xffffffffu, m[j], 8));
                m[j] = fmaxf(m[j], __shfl_xor_sync(0xffffffffu, m[j], 16));
                sl[j][0] = __expf(sl[j][0] - m[j]); sl[j][1] = __expf(sl[j][1] - m[j]);
                sl[j][2] = __expf(sl[j][2] - m[j]); sl[j][3] = __expf(sl[j][3] - m[j]);
                sum[j] = sl[j][0] + sl[j][1] + sl[j][2] + sl[j][3];
                sum[j] += __shfl_xor_sync(0xffffffffu, sum[j], 4);
                sum[j] += __shfl_xor_sync(0xffffffffu, sum[j], 8);
                sum[j] += __shfl_xor_sync(0xffffffffu, sum[j], 16);
                const float f = 1.f / sum[j];
                sl[j][0] *= f; sl[j][1] *= f; sl[j][2] *= f; sl[j][3] *= f;
                Sr[0] += sl[j][0]; Sr[1] += sl[j][1];
                Sr[2] += sl[j][2]; Sr[3] += sl[j][3];
            }
            // ---- A write (fp16 single, conflict-free STS.32) ----
            #pragma unroll
            for (int i = 0; i < 4; i++) {
                const int k = (i < 2) ? (g + 8 * i) : (16 + g + 8 * (i - 2));
                #pragma unroll
                for (int jp = 0; jp < 2; jp++) {
                    __half2 H = __floats2half2_rn(sl[jp * 2 + 0][i], sl[jp * 2 + 1][i]);
                    *reinterpret_cast<__half2*>(&s.ahi[k * AP + nb + jp * 8 + 2 * t]) = H;
                }
            }
            barsync(4, 256);   // A complete

            // ---- GEMM2: E^T[d][k] += (X_hi + X_lo) * A ----
            #pragma unroll
            for (int kn = 0; kn < 8; kn++) {
                const int nn = kn * 16;
                uint32_t Xh[4], Xl[4];
                ldsm4(Xh, sptr(&xh[(16 * hw + lr) * XP + nn + lh * 8]));
                ldsm4(Xl, sptr(&xl[(16 * hw + lr) * XP + nn + lh * 8]));
                uint32_t b0h[4], b1h[4];
                ldsm4(b0h, sptr(&s.ahi[brow * AP + nn + bcol]));
                ldsm4(b1h, sptr(&s.ahi[(16 + brow) * AP + nn + bcol]));
                mma16816(e[0], Xh, b0h + 0); mma16816(e[0], Xl, b0h + 0);
                mma16816(e[1], Xh, b0h + 2); mma16816(e[1], Xl, b0h + 2);
                mma16816(e[2], Xh, b1h + 0); mma16816(e[2], Xl, b1h + 0);
                mma16816(e[3], Xh, b1h + 2); mma16816(e[3], Xl, b1h + 2);
            }
            bararrive(2 + bi, 384);

            // ---- unit epilogue ----
            if ((tl & 3) == 3) {
                #pragma unroll
                for (int i = 0; i < 4; i++) {
                    Sr[i] += __shfl_xor_sync(0xffffffffu, Sr[i], 1);
                    Sr[i] += __shfl_xor_sync(0xffffffffu, Sr[i], 2);
                }
                if (t == 0) {
                    s.Spart[hw * 32 + g]      = Sr[0];
                    s.Spart[hw * 32 + g + 8]  = Sr[1];
                    s.Spart[hw * 32 + g + 16] = Sr[2];
                    s.Spart[hw * 32 + g + 24] = Sr[3];
                }
                Sr[0] = 0.f; Sr[1] = 0.f; Sr[2] = 0.f; Sr[3] = 0.f;
                barsync(4, 256);
                float* outb = out + (size_t)(u >> 5) * 4096;
                #pragma unroll
                for (int j = 0; j < 4; j++) {
                    const int k0 = j * 8 + 2 * t, d0 = 16 * hw + g;
                    float S0 = 0.f, S1 = 0.f;
                    #pragma unroll
                    for (int q = 0; q < 8; q++) {
                        S0 += s.Spart[q * 32 + k0];
                        S1 += s.Spart[q * 32 + k0 + 1];
                    }
                    atomicAdd(&outb[k0 * 128 + d0],            e[j][0] - S0 * Cg[k0 * 128 + d0]);
                    atomicAdd(&outb[(k0 + 1) * 128 + d0],      e[j][1] - S1 * Cg[(k0 + 1) * 128 + d0]);
                    atomicAdd(&outb[k0 * 128 + d0 + 8],        e[j][2] - S0 * Cg[k0 * 128 + d0 + 8]);
                    atomicAdd(&outb[(k0 + 1) * 128 + d0 + 8],  e[j][3] - S1 * Cg[(k0 + 1) * 128 + d0 + 8]);
                    e[j][0] = 0.f; e[j][1] = 0.f; e[j][2] = 0.f; e[j][3] = 0.f;
                }
            }
        }
    }
}

extern "C" void kernel_launch(void* const* d_in, const int* in_sizes, int n_in,
                              void* d_out, int out_size) {
    const float* X  = (const float*)d_in[0];
    const float* C  = (const float*)d_in[1];
    const float* sc = (const float*)d_in[2];
    float* out = (float*)d_out;

    int dev = 0, sms = 0;
    cudaGetDevice(&dev);
    cudaDeviceGetAttribute(&sms, cudaDevAttrMultiProcessorCount, dev);
    if (sms <= 0) sms = 148;

    cudaFuncSetAttribute(enc_kernel, cudaFuncAttributeMaxDynamicSharedMemorySize,
                         (int)sizeof(Sm));
    cudaMemsetAsync(out, 0, (size_t)out_size * sizeof(float));
    enc_kernel<<<sms, 384, sizeof(Sm)>>>(X, C, sc, out);
}

// round 13
// speedup vs baseline: 1.7615x; 1.1238x over previous
#include <cuda_runtime.h>
#include <cuda_fp16.h>
#include <cstdint>

#define XP 136
#define AP 136
#define CP 136

struct Sm {
    __half xhi[2][128 * XP];
    __half chi[32 * CP];
    __half ahi[32 * AP];
    float x2[2][128];
    float x2p[512];
    float Spart[8 * 32];
    float c2[32], scl[32];
};

static __device__ __forceinline__ uint32_t sptr(const void* p) {
    return (uint32_t)__cvta_generic_to_shared(p);
}
static __device__ __forceinline__ void ldsm4(uint32_t* r, uint32_t a) {
    asm volatile("ldmatrix.sync.aligned.m8n8.x4.shared.b16 {%0,%1,%2,%3},[%4];"
                 : "=r"(r[0]), "=r"(r[1]), "=r"(r[2]), "=r"(r[3]) : "r"(a));
}
static __device__ __forceinline__ void ldsm4t(uint32_t* r, uint32_t a) {
    asm volatile("ldmatrix.sync.aligned.m8n8.x4.trans.shared.b16 {%0,%1,%2,%3},[%4];"
                 : "=r"(r[0]), "=r"(r[1]), "=r"(r[2]), "=r"(r[3]) : "r"(a));
}
static __device__ __forceinline__ void mma16816(float* c, const uint32_t* a, const uint32_t* b) {
    asm volatile(
        "mma.sync.aligned.m16n8k16.row.col.f32.f16.f16.f32 "
        "{%0,%1,%2,%3},{%4,%5,%6,%7},{%8,%9},{%0,%1,%2,%3};"
        : "+f"(c[0]), "+f"(c[1]), "+f"(c[2]), "+f"(c[3])
        : "r"(a[0]), "r"(a[1]), "r"(a[2]), "r"(a[3]), "r"(b[0]), "r"(b[1]));
}
static __device__ __forceinline__ void barsync(int id, int cnt) {
    asm volatile("bar.sync %0, %1;" :: "r"(id), "r"(cnt) : "memory");
}
static __device__ __forceinline__ void bararrive(int id, int cnt) {
    asm volatile("bar.arrive %0, %1;" :: "r"(id), "r"(cnt) : "memory");
}

// bars: EMPTY0/1=2/3 (384), heavy=4 (256), prod=5 (128), FULL0/1=6/7 (384)

__global__ void __launch_bounds__(384, 1)
enc_kernel(const float* __restrict__ X, const float* __restrict__ Cg,
           const float* __restrict__ scaleg, float* __restrict__ out)
{
    extern __shared__ char raw[];
    Sm& s = *reinterpret_cast<Sm*>(raw);
    const int tid = threadIdx.x, lane = tid & 31, w = tid >> 5;

    for (int i = tid; i < 4096; i += 384) {
        int k = i >> 7, d = i & 127;
        s.chi[k * CP + d] = __float2half(Cg[i]);
    }
    if (tid < 32) {
        float c2 = 0.f;
        #pragma unroll 8
        for (int d = 0; d < 128; d++) { float c = Cg[tid * 128 + d]; c2 += c * c; }
        s.c2[tid] = c2;
        s.scl[tid] = scaleg[tid];
    }
    __syncthreads();

    const int nq = (1024 - (int)blockIdx.x + (int)gridDim.x - 1) / (int)gridDim.x;
    const int TL = nq * 4;

    if (w < 4) {
        // ================= PRODUCER (warps 0-3), software-pipelined =================
        const int nl = lane * 4;
        float4 va[16];
        {
            const int u = blockIdx.x;
            const float* base = X + (size_t)(u >> 5) * (128 * 16384) + (u & 31) * 512 + nl;
            #pragma unroll
            for (int i = 0; i < 16; i++)
                va[i] = *reinterpret_cast<const float4*>(base + (size_t)(w * 32 + i) * 16384);
        }
        for (int tl = 0; tl < TL; tl++) {
            const int bi = tl & 1;
            const int u = blockIdx.x + (tl >> 2) * gridDim.x;
            const float* base = X + (size_t)(u >> 5) * (128 * 16384)
                              + (u & 31) * 512 + (tl & 3) * 128 + nl;
            barsync(2 + bi, 384);
            float4 vb[16];
            #pragma unroll
            for (int i = 0; i < 16; i++)
                vb[i] = *reinterpret_cast<const float4*>(base + (size_t)(w * 32 + 16 + i) * 16384);
            __half* xh = s.xhi[bi];
            float p0 = 0.f, p1 = 0.f, p2 = 0.f, p3 = 0.f;
            #pragma unroll
            for (int i = 0; i < 16; i++) {
                const int d = w * 32 + i;
                const float4 v = va[i];
                __half2 H0 = __floats2half2_rn(v.x, v.y);
                __half2 H1 = __floats2half2_rn(v.z, v.w);
                *reinterpret_cast<__half2*>(&xh[d * XP + nl])     = H0;
                *reinterpret_cast<__half2*>(&xh[d * XP + nl + 2]) = H1;
                p0 = fmaf(v.x, v.x, p0); p1 = fmaf(v.y, v.y, p1);
                p2 = fmaf(v.z, v.z, p2); p3 = fmaf(v.w, v.w, p3);
            }
            #pragma unroll
            for (int i = 0; i < 16; i++) {
                const int d = w * 32 + 16 + i;
                const float4 v = vb[i];
                __half2 H0 = __floats2half2_rn(v.x, v.y);
                __half2 H1 = __floats2half2_rn(v.z, v.w);
                *reinterpret_cast<__half2*>(&xh[d * XP + nl])     = H0;
                *reinterpret_cast<__half2*>(&xh[d * XP + nl + 2]) = H1;
                p0 = fmaf(v.x, v.x, p0); p1 = fmaf(v.y, v.y, p1);
                p2 = fmaf(v.z, v.z, p2); p3 = fmaf(v.w, v.w, p3);
            }
            *reinterpret_cast<float4*>(&s.x2p[w * 128 + nl]) = make_float4(p0, p1, p2, p3);
            barsync(5, 128);
            s.x2[bi][tid] = s.x2p[tid] + s.x2p[128 + tid] + s.x2p[256 + tid] + s.x2p[384 + tid];
            __threadfence_block();
            bararrive(6 + bi, 384);
            if (tl + 1 < TL) {
                const int u2 = blockIdx.x + ((tl + 1) >> 2) * gridDim.x;
                const float* b2 = X + (size_t)(u2 >> 5) * (128 * 16384)
                                + (u2 & 31) * 512 + ((tl + 1) & 3) * 128 + nl;
                #pragma unroll
                for (int i = 0; i < 16; i++)
                    va[i] = *reinterpret_cast<const float4*>(b2 + (size_t)(w * 32 + i) * 16384);
            }
        }
    } else {
        // ================= HEAVY (warps 4-11) =================
        const int hw = w - 4;
        const int g = lane >> 2, t = lane & 3;
        const int lr = lane & 15, lh = lane >> 4;
        const int brow = (lane >> 4) * 8 + (lane & 7);
        const int bcol = ((lane >> 3) & 1) * 8;
        const int nb = hw * 16;
        const float sc0 = s.scl[g],      cc0 = s.c2[g];
        const float sc1 = s.scl[g + 8],  cc1 = s.c2[g + 8];
        const float sc2 = s.scl[g + 16], cc2 = s.c2[g + 16];
        const float sc3 = s.scl[g + 24], cc3 = s.c2[g + 24];

        // ---- hoist C-fragments into registers (invariant across subtiles) ----
        uint32_t cfr[8][2][4];
        #pragma unroll
        for (int kd = 0; kd < 8; kd++) {
            ldsm4(cfr[kd][0], sptr(&s.chi[lr * CP + kd * 16 + lh * 8]));
            ldsm4(cfr[kd][1], sptr(&s.chi[(16 + lr) * CP + kd * 16 + lh * 8]));
        }
        bararrive(2, 384);
        bararrive(3, 384);

        float e[4][4];
        #pragma unroll
        for (int j = 0; j < 4; j++) { e[j][0] = 0.f; e[j][1] = 0.f; e[j][2] = 0.f; e[j][3] = 0.f; }
        float Sr[4] = {0.f, 0.f, 0.f, 0.f};

        for (int tl = 0; tl < TL; tl++) {
            const int bi = tl & 1;
            const int u = blockIdx.x + (tl >> 2) * gridDim.x;
            barsync(6 + bi, 384);
            const __half* xh = s.xhi[bi];

            // ---- GEMM1: all 32 k for this warp's 16 n ----
            float acc[2][2][4];
            #pragma unroll
            for (int mt = 0; mt < 2; mt++)
                #pragma unroll
                for (int nt = 0; nt < 2; nt++) {
                    acc[mt][nt][0] = 0.f; acc[mt][nt][1] = 0.f;
                    acc[mt][nt][2] = 0.f; acc[mt][nt][3] = 0.f;
                }
            #pragma unroll
            for (int kd = 0; kd < 8; kd++) {
                uint32_t bh[4];
                ldsm4t(bh, sptr(&xh[(kd * 16 + lr) * XP + nb + lh * 8]));
                mma16816(acc[0][0], cfr[kd][0], bh + 0);
                mma16816(acc[0][1], cfr[kd][0], bh + 2);
                mma16816(acc[1][0], cfr[kd][1], bh + 0);
                mma16816(acc[1][1], cfr[kd][1], bh + 2);
            }

            // ---- in-register softmax over k ----
            const float* x2 = s.x2[bi];
            float sl[4][4], m[4], sum[4];
            #pragma unroll
            for (int j = 0; j < 4; j++) {
                const int nt = j >> 1, jc = j & 1;
                const float xv = x2[nb + nt * 8 + 2 * t + jc];
                sl[j][0] = sc0 * (xv - 2.f * acc[0][nt][jc]     + cc0);
                sl[j][1] = sc1 * (xv - 2.f * acc[0][nt][jc + 2] + cc1);
                sl[j][2] = sc2 * (xv - 2.f * acc[1][nt][jc]     + cc2);
                sl[j][3] = sc3 * (xv - 2.f * acc[1][nt][jc + 2] + cc3);
                m[j] = fmaxf(fmaxf(sl[j][0], sl[j][1]), fmaxf(sl[j][2], sl[j][3]));
            }
            #pragma unroll
            for (int j = 0; j < 4; j++) {
                m[j] = fmaxf(m[j], __shfl_xor_sync(0xffffffffu, m[j], 4));
                m[j] = fmaxf(m[j], __shfl_xor_sync(0xffffffffu, m[j], 8));
                m[j] = fmaxf(m[j], __shfl_xor_sync(0xffffffffu, m[j], 16));
                sl[j][0] = __expf(sl[j][0] - m[j]); sl[j][1] = __expf(sl[j][1] - m[j]);
                sl[j][2] = __expf(sl[j][2] - m[j]); sl[j][3] = __expf(sl[j][3] - m[j]);
                sum[j] = sl[j][0] + sl[j][1] + sl[j][2] + sl[j][3];
                sum[j] += __shfl_xor_sync(0xffffffffu, sum[j], 4);
                sum[j] += __shfl_xor_sync(0xffffffffu, sum[j], 8);
                sum[j] += __shfl_xor_sync(0xffffffffu, sum[j], 16);
                const float f = 1.f / sum[j];
                sl[j][0] *= f; sl[j][1] *= f; sl[j][2] *= f; sl[j][3] *= f;
                Sr[0] += sl[j][0]; Sr[1] += sl[j][1];
                Sr[2] += sl[j][2]; Sr[3] += sl[j][3];
            }
            // ---- A write (fp16, conflict-free STS.32) ----
            #pragma unroll
            for (int i = 0; i < 4; i++) {
                const int k = (i < 2) ? (g + 8 * i) : (16 + g + 8 * (i - 2));
                #pragma unroll
                for (int jp = 0; jp < 2; jp++) {
                    __half2 H = __floats2half2_rn(sl[jp * 2 + 0][i], sl[jp * 2 + 1][i]);
                    *reinterpret_cast<__half2*>(&s.ahi[k * AP + nb + jp * 8 + 2 * t]) = H;
                }
            }
            barsync(4, 256);   // A complete

            // ---- GEMM2: E^T[d][k] += X * A ----
            #pragma unroll
            for (int kn = 0; kn < 8; kn++) {
                const int nn = kn * 16;
                uint32_t Xh[4];
                ldsm4(Xh, sptr(&xh[(16 * hw + lr) * XP + nn + lh * 8]));
                uint32_t b0h[4], b1h[4];
                ldsm4(b0h, sptr(&s.ahi[brow * AP + nn + bcol]));
                ldsm4(b1h, sptr(&s.ahi[(16 + brow) * AP + nn + bcol]));
                mma16816(e[0], Xh, b0h + 0);
                mma16816(e[1], Xh, b0h + 2);
                mma16816(e[2], Xh, b1h + 0);
                mma16816(e[3], Xh, b1h + 2);
            }
            bararrive(2 + bi, 384);

            // ---- unit epilogue ----
            if ((tl & 3) == 3) {
                #pragma unroll
                for (int i = 0; i < 4; i++) {
                    Sr[i] += __shfl_xor_sync(0xffffffffu, Sr[i], 1);
                    Sr[i] += __shfl_xor_sync(0xffffffffu, Sr[i], 2);
                }
                if (t == 0) {
                    s.Spart[hw * 32 + g]      = Sr[0];
                    s.Spart[hw * 32 + g + 8]  = Sr[1];
                    s.Spart[hw * 32 + g + 16] = Sr[2];
                    s.Spart[hw * 32 + g + 24] = Sr[3];
                }
                Sr[0] = 0.f; Sr[1] = 0.f; Sr[2] = 0.f; Sr[3] = 0.f;
                barsync(4, 256);
                float* outb = out + (size_t)(u >> 5) * 4096;
                #pragma unroll
                for (int j = 0; j < 4; j++) {
                    const int k0 = j * 8 + 2 * t, d0 = 16 * hw + g;
                    float S0 = 0.f, S1 = 0.f;
                    #pragma unroll
                    for (int q = 0; q < 8; q++) {
                        S0 += s.Spart[q * 32 + k0];
                        S1 += s.Spart[q * 32 + k0 + 1];
                    }
                    atomicAdd(&outb[k0 * 128 + d0],            e[j][0] - S0 * Cg[k0 * 128 + d0]);
                    atomicAdd(&outb[(k0 + 1) * 128 + d0],      e[j][1] - S1 * Cg[(k0 + 1) * 128 + d0]);
                    atomicAdd(&outb[k0 * 128 + d0 + 8],        e[j][2] - S0 * Cg[k0 * 128 + d0 + 8]);
                    atomicAdd(&outb[(k0 + 1) * 128 + d0 + 8],  e[j][3] - S1 * Cg[(k0 + 1) * 128 + d0 + 8]);
                    e[j][0] = 0.f; e[j][1] = 0.f; e[j][2] = 0.f; e[j][3] = 0.f;
                }
            }
        }
    }
}

extern "C" void kernel_launch(void* const* d_in, const int* in_sizes, int n_in,
                              void* d_out, int out_size) {
    const float* X  = (const float*)d_in[0];
    const float* C  = (const float*)d_in[1];
    const float* sc = (const float*)d_in[2];
    float* out = (float*)d_out;

    int dev = 0, sms = 0;
    cudaGetDevice(&dev);
    cudaDeviceGetAttribute(&sms, cudaDevAttrMultiProcessorCount, dev);
    if (sms <= 0) sms = 148;

    cudaFuncSetAttribute(enc_kernel, cudaFuncAttributeMaxDynamicSharedMemorySize,
                         (int)sizeof(Sm));
    cudaMemsetAsync(out, 0, (size_t)out_size * sizeof(float));
    enc_kernel<<<sms, 384, sizeof(Sm)>>>(X, C, sc, out);
}

// round 14
// speedup vs baseline: 1.7678x; 1.0036x over previous
#include <cuda_runtime.h>
#include <cuda_fp16.h>
#include <cstdint>

#define XP 136
#define AP 136
#define CP 136

struct Sm {
    __half xhi[2][128 * XP];
    __half chi[32 * CP];
    __half ahi[32 * AP];
    float x2[2][128];
    float x2p[1024];
    float Spart[8 * 32];
    float c2[32], scl[32];
};

static __device__ __forceinline__ uint32_t sptr(const void* p) {
    return (uint32_t)__cvta_generic_to_shared(p);
}
static __device__ __forceinline__ void ldsm4(uint32_t* r, uint32_t a) {
    asm volatile("ldmatrix.sync.aligned.m8n8.x4.shared.b16 {%0,%1,%2,%3},[%4];"
                 : "=r"(r[0]), "=r"(r[1]), "=r"(r[2]), "=r"(r[3]) : "r"(a));
}
static __device__ __forceinline__ void ldsm4t(uint32_t* r, uint32_t a) {
    asm volatile("ldmatrix.sync.aligned.m8n8.x4.trans.shared.b16 {%0,%1,%2,%3},[%4];"
                 : "=r"(r[0]), "=r"(r[1]), "=r"(r[2]), "=r"(r[3]) : "r"(a));
}
static __device__ __forceinline__ void mma16816(float* c, const uint32_t* a, const uint32_t* b) {
    asm volatile(
        "mma.sync.aligned.m16n8k16.row.col.f32.f16.f16.f32 "
        "{%0,%1,%2,%3},{%4,%5,%6,%7},{%8,%9},{%0,%1,%2,%3};"
        : "+f"(c[0]), "+f"(c[1]), "+f"(c[2]), "+f"(c[3])
        : "r"(a[0]), "r"(a[1]), "r"(a[2]), "r"(a[3]), "r"(b[0]), "r"(b[1]));
}
static __device__ __forceinline__ void barsync(int id, int cnt) {
    asm volatile("bar.sync %0, %1;" :: "r"(id), "r"(cnt) : "memory");
}
static __device__ __forceinline__ void bararrive(int id, int cnt) {
    asm volatile("bar.arrive %0, %1;" :: "r"(id), "r"(cnt) : "memory");
}

// bars: EMPTY0/1=2/3 (512), heavy=4 (256), prod=5 (256), FULL0/1=6/7 (512)

__global__ void __launch_bounds__(512, 1)
enc_kernel(const float* __restrict__ X, const float* __restrict__ Cg,
           const float* __restrict__ scaleg, float* __restrict__ out)
{
    extern __shared__ char raw[];
    Sm& s = *reinterpret_cast<Sm*>(raw);
    const int tid = threadIdx.x, lane = tid & 31, w = tid >> 5;

    for (int i = tid; i < 4096; i += 512) {
        int k = i >> 7, d = i & 127;
        s.chi[k * CP + d] = __float2half(Cg[i]);
    }
    if (tid < 32) {
        float c2 = 0.f;
        #pragma unroll 8
        for (int d = 0; d < 128; d++) { float c = Cg[tid * 128 + d]; c2 += c * c; }
        s.c2[tid] = c2;
        s.scl[tid] = scaleg[tid];
    }
    __syncthreads();

    const int nq = (1024 - (int)blockIdx.x + (int)gridDim.x - 1) / (int)gridDim.x;
    const int TL = nq * 4;

    if (w < 8) {
        // ========= PRODUCER (warps 0-7): 16 d-rows each, software-pipelined =========
        const int nl = lane * 4;
        float4 va[8];
        {
            const int u = blockIdx.x;
            const float* base = X + (size_t)(u >> 5) * (128 * 16384) + (u & 31) * 512 + nl;
            #pragma unroll
            for (int i = 0; i < 8; i++)
                va[i] = *reinterpret_cast<const float4*>(base + (size_t)(w * 16 + i) * 16384);
        }
        for (int tl = 0; tl < TL; tl++) {
            const int bi = tl & 1;
            const int u = blockIdx.x + (tl >> 2) * gridDim.x;
            const float* base = X + (size_t)(u >> 5) * (128 * 16384)
                              + (u & 31) * 512 + (tl & 3) * 128 + nl;
            barsync(2 + bi, 512);
            float4 vb[8];
            #pragma unroll
            for (int i = 0; i < 8; i++)
                vb[i] = *reinterpret_cast<const float4*>(base + (size_t)(w * 16 + 8 + i) * 16384);
            __half* xh = s.xhi[bi];
            float p0 = 0.f, p1 = 0.f, p2 = 0.f, p3 = 0.f;
            #pragma unroll
            for (int i = 0; i < 8; i++) {
                const int d = w * 16 + i;
                const float4 v = va[i];
                __half2 H0 = __floats2half2_rn(v.x, v.y);
                __half2 H1 = __floats2half2_rn(v.z, v.w);
                *reinterpret_cast<__half2*>(&xh[d * XP + nl])     = H0;
                *reinterpret_cast<__half2*>(&xh[d * XP + nl + 2]) = H1;
                p0 = fmaf(v.x, v.x, p0); p1 = fmaf(v.y, v.y, p1);
                p2 = fmaf(v.z, v.z, p2); p3 = fmaf(v.w, v.w, p3);
            }
            #pragma unroll
            for (int i = 0; i < 8; i++) {
                const int d = w * 16 + 8 + i;
                const float4 v = vb[i];
                __half2 H0 = __floats2half2_rn(v.x, v.y);
                __half2 H1 = __floats2half2_rn(v.z, v.w);
                *reinterpret_cast<__half2*>(&xh[d * XP + nl])     = H0;
                *reinterpret_cast<__half2*>(&xh[d * XP + nl + 2]) = H1;
                p0 = fmaf(v.x, v.x, p0); p1 = fmaf(v.y, v.y, p1);
                p2 = fmaf(v.z, v.z, p2); p3 = fmaf(v.w, v.w, p3);
            }
            *reinterpret_cast<float4*>(&s.x2p[w * 128 + nl]) = make_float4(p0, p1, p2, p3);
            barsync(5, 256);
            if (tid < 128) {
                float sum = 0.f;
                #pragma unroll
                for (int q = 0; q < 8; q++) sum += s.x2p[q * 128 + tid];
                s.x2[bi][tid] = sum;
            }
            __threadfence_block();
            bararrive(6 + bi, 512);
            if (tl + 1 < TL) {
                const int u2 = blockIdx.x + ((tl + 1) >> 2) * gridDim.x;
                const float* b2 = X + (size_t)(u2 >> 5) * (128 * 16384)
                                + (u2 & 31) * 512 + ((tl + 1) & 3) * 128 + nl;
                #pragma unroll
                for (int i = 0; i < 8; i++)
                    va[i] = *reinterpret_cast<const float4*>(b2 + (size_t)(w * 16 + i) * 16384);
            }
        }
    } else {
        // ================= HEAVY (warps 8-15) =================
        const int hw = w - 8;
        const int g = lane >> 2, t = lane & 3;
        const int lr = lane & 15, lh = lane >> 4;
        const int brow = (lane >> 4) * 8 + (lane & 7);
        const int bcol = ((lane >> 3) & 1) * 8;
        const int nb = hw * 16;
        const float sc0 = s.scl[g],      cc0 = s.c2[g];
        const float sc1 = s.scl[g + 8],  cc1 = s.c2[g + 8];
        const float sc2 = s.scl[g + 16], cc2 = s.c2[g + 16];
        const float sc3 = s.scl[g + 24], cc3 = s.c2[g + 24];

        // partial C-fragment hoist (kd 0..3) — fits the 512-thread reg budget
        uint32_t cfr[4][2][4];
        #pragma unroll
        for (int kd = 0; kd < 4; kd++) {
            ldsm4(cfr[kd][0], sptr(&s.chi[lr * CP + kd * 16 + lh * 8]));
            ldsm4(cfr[kd][1], sptr(&s.chi[(16 + lr) * CP + kd * 16 + lh * 8]));
        }
        bararrive(2, 512);
        bararrive(3, 512);

        float e[4][4];
        #pragma unroll
        for (int j = 0; j < 4; j++) { e[j][0] = 0.f; e[j][1] = 0.f; e[j][2] = 0.f; e[j][3] = 0.f; }
        float Sr[4] = {0.f, 0.f, 0.f, 0.f};

        for (int tl = 0; tl < TL; tl++) {
            const int bi = tl & 1;
            const int u = blockIdx.x + (tl >> 2) * gridDim.x;
            barsync(6 + bi, 512);
            const __half* xh = s.xhi[bi];

            // ---- GEMM1: all 32 k for this warp's 16 n ----
            float acc[2][2][4];
            #pragma unroll
            for (int mt = 0; mt < 2; mt++)
                #pragma unroll
                for (int nt = 0; nt < 2; nt++) {
                    acc[mt][nt][0] = 0.f; acc[mt][nt][1] = 0.f;
                    acc[mt][nt][2] = 0.f; acc[mt][nt][3] = 0.f;
                }
            #pragma unroll
            for (int kd = 0; kd < 4; kd++) {
                uint32_t bh[4];
                ldsm4t(bh, sptr(&xh[(kd * 16 + lr) * XP + nb + lh * 8]));
                mma16816(acc[0][0], cfr[kd][0], bh + 0);
                mma16816(acc[0][1], cfr[kd][0], bh + 2);
                mma16816(acc[1][0], cfr[kd][1], bh + 0);
                mma16816(acc[1][1], cfr[kd][1], bh + 2);
            }
            #pragma unroll
            for (int kd = 4; kd < 8; kd++) {
                uint32_t a0[4], a1[4], bh[4];
                ldsm4(a0, sptr(&s.chi[lr * CP + kd * 16 + lh * 8]));
                ldsm4(a1, sptr(&s.chi[(16 + lr) * CP + kd * 16 + lh * 8]));
                ldsm4t(bh, sptr(&xh[(kd * 16 + lr) * XP + nb + lh * 8]));
                mma16816(acc[0][0], a0, bh + 0);
                mma16816(acc[0][1], a0, bh + 2);
                mma16816(acc[1][0], a1, bh + 0);
                mma16816(acc[1][1], a1, bh + 2);
            }

            // ---- in-register softmax over k ----
            const float* x2 = s.x2[bi];
            float sl[4][4], m[4], sum[4];
            #pragma unroll
            for (int j = 0; j < 4; j++) {
                const int nt = j >> 1, jc = j & 1;
                const float xv = x2[nb + nt * 8 + 2 * t + jc];
                sl[j][0] = sc0 * (xv - 2.f * acc[0][nt][jc]     + cc0);
                sl[j][1] = sc1 * (xv - 2.f * acc[0][nt][jc + 2] + cc1);
                sl[j][2] = sc2 * (xv - 2.f * acc[1][nt][jc]     + cc2);
                sl[j][3] = sc3 * (xv - 2.f * acc[1][nt][jc + 2] + cc3);
                m[j] = fmaxf(fmaxf(sl[j][0], sl[j][1]), fmaxf(sl[j][2], sl[j][3]));
            }
            #pragma unroll
            for (int j = 0; j < 4; j++) {
                m[j] = fmaxf(m[j], __shfl_xor_sync(0xffffffffu, m[j], 4));
                m[j] = fmaxf(m[j], __shfl_xor_sync(0xffffffffu, m[j], 8));
                m[j] = fmaxf(m[j], __shfl_xor_sync(0xffffffffu, m[j], 16));
                sl[j][0] = __expf(sl[j][0] - m[j]); sl[j][1] = __expf(sl[j][1] - m[j]);
                sl[j][2] = __expf(sl[j][2] - m[j]); sl[j][3] = __expf(sl[j][3] - m[j]);
                sum[j] = sl[j][0] + sl[j][1] + sl[j][2] + sl[j][3];
                sum[j] += __shfl_xor_sync(0xffffffffu, sum[j], 4);
                sum[j] += __shfl_xor_sync(0xffffffffu, sum[j], 8);
                sum[j] += __shfl_xor_sync(0xffffffffu, sum[j], 16);
                const float f = 1.f / sum[j];
                sl[j][0] *= f; sl[j][1] *= f; sl[j][2] *= f; sl[j][3] *= f;
                Sr[0] += sl[j][0]; Sr[1] += sl[j][1];
                Sr[2] += sl[j][2]; Sr[3] += sl[j][3];
            }
            // ---- A write (fp16, conflict-free STS.32) ----
            #pragma unroll
            for (int i = 0; i < 4; i++) {
                const int k = (i < 2) ? (g + 8 * i) : (16 + g + 8 * (i - 2));
                #pragma unroll
                for (int jp = 0; jp < 2; jp++) {
                    __half2 H = __floats2half2_rn(sl[jp * 2 + 0][i], sl[jp * 2 + 1][i]);
                    *reinterpret_cast<__half2*>(&s.ahi[k * AP + nb + jp * 8 + 2 * t]) = H;
                }
            }
            barsync(4, 256);   // A complete

            // ---- GEMM2: E^T[d][k] += X * A ----
            #pragma unroll
            for (int kn = 0; kn < 8; kn++) {
                const int nn = kn * 16;
                uint32_t Xh[4];
                ldsm4(Xh, sptr(&xh[(16 * hw + lr) * XP + nn + lh * 8]));
                uint32_t b0h[4], b1h[4];
                ldsm4(b0h, sptr(&s.ahi[brow * AP + nn + bcol]));
                ldsm4(b1h, sptr(&s.ahi[(16 + brow) * AP + nn + bcol]));
                mma16816(e[0], Xh, b0h + 0);
                mma16816(e[1], Xh, b0h + 2);
                mma16816(e[2], Xh, b1h + 0);
                mma16816(e[3], Xh, b1h + 2);
            }
            bararrive(2 + bi, 512);

            // ---- unit epilogue ----
            if ((tl & 3) == 3) {
                #pragma unroll
                for (int i = 0; i < 4; i++) {
                    Sr[i] += __shfl_xor_sync(0xffffffffu, Sr[i], 1);
                    Sr[i] += __shfl_xor_sync(0xffffffffu, Sr[i], 2);
                }
                if (t == 0) {
                    s.Spart[hw * 32 + g]      = Sr[0];
                    s.Spart[hw * 32 + g + 8]  = Sr[1];
                    s.Spart[hw * 32 + g + 16] = Sr[2];
                    s.Spart[hw * 32 + g + 24] = Sr[3];
                }
                Sr[0] = 0.f; Sr[1] = 0.f; Sr[2] = 0.f; Sr[3] = 0.f;
                barsync(4, 256);
                float* outb = out + (size_t)(u >> 5) * 4096;
                #pragma unroll
                for (int j = 0; j < 4; j++) {
                    const int k0 = j * 8 + 2 * t, d0 = 16 * hw + g;
                    float S0 = 0.f, S1 = 0.f;
                    #pragma unroll
                    for (int q = 0; q < 8; q++) {
                        S0 += s.Spart[q * 32 + k0];
                        S1 += s.Spart[q * 32 + k0 + 1];
                    }
                    atomicAdd(&outb[k0 * 128 + d0],            e[j][0] - S0 * Cg[k0 * 128 + d0]);
                    atomicAdd(&outb[(k0 + 1) * 128 + d0],      e[j][1] - S1 * Cg[(k0 + 1) * 128 + d0]);
                    atomicAdd(&outb[k0 * 128 + d0 + 8],        e[j][2] - S0 * Cg[k0 * 128 + d0 + 8]);
                    atomicAdd(&outb[(k0 + 1) * 128 + d0 + 8],  e[j][3] - S1 * Cg[(k0 + 1) * 128 + d0 + 8]);
                    e[j][0] = 0.f; e[j][1] = 0.f; e[j][2] = 0.f; e[j][3] = 0.f;
                }
            }
        }
    }
}

extern "C" void kernel_launch(void* const* d_in, const int* in_sizes, int n_in,
                              void* d_out, int out_size) {
    const float* X  = (const float*)d_in[0];
    const float* C  = (const float*)d_in[1];
    const float* sc = (const float*)d_in[2];
    float* out = (float*)d_out;

    int dev = 0, sms = 0;
    cudaGetDevice(&dev);
    cudaDeviceGetAttribute(&sms, cudaDevAttrMultiProcessorCount, dev);
    if (sms <= 0) sms = 148;

    cudaFuncSetAttribute(enc_kernel, cudaFuncAttributeMaxDynamicSharedMemorySize,
                         (int)sizeof(Sm));
    cudaMemsetAsync(out, 0, (size_t)out_size * sizeof(float));
    enc_kernel<<<sms, 512, sizeof(Sm)>>>(X, C, sc, out);
}